// round 14
// baseline (speedup 1.0000x reference)
#include <cuda_runtime.h>
#include <cstdint>

// y[4096] = x[1,5504] @ W[4096, act_idx[cluster]]^T + bias
// 128 blocks x 1024 threads, 32 contiguous rows/block, one warp per row,
// per-block densified xs[11008] in smem, W prefetch before prologue.
// L2 eviction-priority via the sm_10x 256-bit load path (the only form that
// accepts L2::evict_* on this toolchain):
//   resident rows ((row & 15) < 8, ~90MB): ld.global.nc.L2::evict_last.v8.b32
//   streamed rows:                          ld.global.nc.L2::evict_first.v8.b32
// 256-bit loads also halve LDG count (1KB per warp per load).

#define D_OUT 4096
#define D_IN 11008
#define NF8 (D_IN / 8)      // 1376 float8 chunks per row; 1376 = 32*43
#define REMAINED 5504
#define ROWS_PER_BLOCK 32
#define THREADS 1024
#define NBLOCKS (D_OUT / ROWS_PER_BLOCK)   // 128

__device__ __forceinline__ void ld256_last(const float* p, float4& a, float4& b) {
    uint32_t r0,r1,r2,r3,r4,r5,r6,r7;
    asm("ld.global.nc.L2::evict_last.v8.b32 {%0,%1,%2,%3,%4,%5,%6,%7}, [%8];"
        : "=r"(r0),"=r"(r1),"=r"(r2),"=r"(r3),
          "=r"(r4),"=r"(r5),"=r"(r6),"=r"(r7) : "l"(p));
    a.x=__uint_as_float(r0); a.y=__uint_as_float(r1);
    a.z=__uint_as_float(r2); a.w=__uint_as_float(r3);
    b.x=__uint_as_float(r4); b.y=__uint_as_float(r5);
    b.z=__uint_as_float(r6); b.w=__uint_as_float(r7);
}
__device__ __forceinline__ void ld256_first(const float* p, float4& a, float4& b) {
    uint32_t r0,r1,r2,r3,r4,r5,r6,r7;
    asm("ld.global.nc.L2::evict_first.v8.b32 {%0,%1,%2,%3,%4,%5,%6,%7}, [%8];"
        : "=r"(r0),"=r"(r1),"=r"(r2),"=r"(r3),
          "=r"(r4),"=r"(r5),"=r"(r6),"=r"(r7) : "l"(p));
    a.x=__uint_as_float(r0); a.y=__uint_as_float(r1);
    a.z=__uint_as_float(r2); a.w=__uint_as_float(r3);
    b.x=__uint_as_float(r4); b.y=__uint_as_float(r5);
    b.z=__uint_as_float(r6); b.w=__uint_as_float(r7);
}

__global__ __launch_bounds__(THREADS, 1) void fused_gemv_kernel(
    const float* __restrict__ x,
    const float* __restrict__ weight,
    const float* __restrict__ bias,
    const int*   __restrict__ act_idx,
    const int*   __restrict__ cluster,
    float*       __restrict__ out)
{
    __shared__ float sxs[D_IN];  // 44032 bytes

    const int warp = threadIdx.x >> 5;
    const int lane = threadIdx.x & 31;
    const int row  = blockIdx.x * ROWS_PER_BLOCK + warp;
    const bool resident = (row & 15) < 8;   // 2048 rows (~90MB) L2-resident

    const float* __restrict__ wrow = weight + (size_t)row * D_IN;

    // ---- prefetch first two iterations (2 x 32B per lane) before prologue ----
    float4 pa0, pb0, pa1, pb1;
    if (resident) {
        ld256_last (wrow + lane * 8,            pa0, pb0);
        ld256_last (wrow + (lane + 32) * 8,     pa1, pb1);
    } else {
        ld256_first(wrow + lane * 8,            pa0, pb0);
        ld256_first(wrow + (lane + 32) * 8,     pa1, pb1);
    }

    // ---- prologue: zero smem, densify xs ----
    float4* sxs4 = reinterpret_cast<float4*>(sxs);
    #pragma unroll
    for (int i = threadIdx.x; i < D_IN / 4; i += THREADS)
        sxs4[i] = make_float4(0.f, 0.f, 0.f, 0.f);
    __syncthreads();

    const int cl = *cluster;
    const int* idx_row = act_idx + cl * REMAINED;
    #pragma unroll
    for (int i = threadIdx.x; i < REMAINED; i += THREADS) {
        int   c = __ldg(idx_row + i);
        float v = __ldg(x + i);
        atomicAdd(&sxs[c], v);
    }
    __syncthreads();

    // ---- dense GEMV: 43 float8-iterations per warp (first two peeled) ----
    const float4* sx4 = reinterpret_cast<const float4*>(sxs);

    float acc0, acc1;
    {
        float4 b0 = sx4[lane * 2],     b1 = sx4[lane * 2 + 1];
        float4 b2 = sx4[(lane+32) * 2], b3 = sx4[(lane+32) * 2 + 1];
        acc0 = fmaf(pa0.x, b0.x, fmaf(pa0.y, b0.y, fmaf(pa0.z, b0.z, pa0.w * b0.w)));
        acc1 = fmaf(pb0.x, b1.x, fmaf(pb0.y, b1.y, fmaf(pb0.z, b1.z, pb0.w * b1.w)));
        acc0 = fmaf(pa1.x, b2.x, fmaf(pa1.y, b2.y, fmaf(pa1.z, b2.z, fmaf(pa1.w, b2.w, acc0))));
        acc1 = fmaf(pb1.x, b3.x, fmaf(pb1.y, b3.y, fmaf(pb1.z, b3.z, fmaf(pb1.w, b3.w, acc1))));
    }

    static_assert(NF8 == 32 * 43, "expect 43 warp-iterations");
    if (resident) {
        #pragma unroll 4
        for (int i = lane + 64; i < NF8; i += 32) {
            float4 a, b;
            ld256_last(wrow + i * 8, a, b);
            float4 c0 = sx4[i * 2], c1 = sx4[i * 2 + 1];
            acc0 = fmaf(a.x, c0.x, acc0);
            acc0 = fmaf(a.y, c0.y, acc0);
            acc0 = fmaf(a.z, c0.z, acc0);
            acc0 = fmaf(a.w, c0.w, acc0);
            acc1 = fmaf(b.x, c1.x, acc1);
            acc1 = fmaf(b.y, c1.y, acc1);
            acc1 = fmaf(b.z, c1.z, acc1);
            acc1 = fmaf(b.w, c1.w, acc1);
        }
    } else {
        #pragma unroll 4
        for (int i = lane + 64; i < NF8; i += 32) {
            float4 a, b;
            ld256_first(wrow + i * 8, a, b);
            float4 c0 = sx4[i * 2], c1 = sx4[i * 2 + 1];
            acc0 = fmaf(a.x, c0.x, acc0);
            acc0 = fmaf(a.y, c0.y, acc0);
            acc0 = fmaf(a.z, c0.z, acc0);
            acc0 = fmaf(a.w, c0.w, acc0);
            acc1 = fmaf(b.x, c1.x, acc1);
            acc1 = fmaf(b.y, c1.y, acc1);
            acc1 = fmaf(b.z, c1.z, acc1);
            acc1 = fmaf(b.w, c1.w, acc1);
        }
    }

    float acc = acc0 + acc1;
    #pragma unroll
    for (int off = 16; off > 0; off >>= 1)
        acc += __shfl_xor_sync(0xffffffffu, acc, off);

    if (lane == 0)
        out[row] = acc + bias[row];
}

extern "C" void kernel_launch(void* const* d_in, const int* in_sizes, int n_in,
                              void* d_out, int out_size) {
    const float* x       = (const float*)d_in[0];   // (1, 5504)
    const float* weight  = (const float*)d_in[1];   // (4096, 11008)
    const float* bias    = (const float*)d_in[2];   // (4096,)
    const int*   act_idx = (const int*)d_in[3];     // (64, 5504) int32 (jax x64 off)
    const int*   cluster = (const int*)d_in[4];     // scalar int32
    float*       out     = (float*)d_out;           // (1, 4096)

    fused_gemv_kernel<<<NBLOCKS, THREADS>>>(x, weight, bias, act_idx, cluster, out);
}